// round 5
// baseline (speedup 1.0000x reference)
#include <cuda_runtime.h>
#include <cuda_bf16.h>
#include <math.h>
#include <stdint.h>

#define P_N 256
#define L_N 64
#define I_DIM 512
#define H_DIM 1024
#define G4 4096
#define ROWS (P_N * L_N)  // 16384

// ---- scratch ----
__device__ __align__(128) __nv_bfloat16 g_xWb[(size_t)ROWS * G4];       // x@W_ih^T+b, bf16
__device__ __align__(128) __nv_bfloat16 g_x[(size_t)ROWS * I_DIM];      // gathered emb, bf16
__device__ __align__(128) __nv_bfloat16 g_Whh_b[(size_t)G4 * H_DIM];    // permuted rows, bf16
__device__ __align__(128) __nv_bfloat16 g_Wih_b[(size_t)G4 * I_DIM];    // permuted rows, bf16
__device__ float g_bias_p[G4];
__device__ __align__(128) __nv_bfloat16 g_hb[2][P_N * H_DIM];           // hidden, bf16
__device__ float g_final[P_N * H_DIM];
__device__ float g_v[P_N * H_DIM];
__device__ float g_attn[P_N * H_DIM];
__device__ float g_pooled[H_DIM];
__device__ volatile unsigned g_flags[128];                              // step barrier

__device__ __forceinline__ float sigm(float x) { return 1.0f / (1.0f + expf(-x)); }

__device__ __forceinline__ uint32_t smem_u32(const void* p) {
    uint32_t a;
    asm("{ .reg .u64 t; cvta.to.shared.u64 t, %1; cvt.u32.u64 %0, t; }" : "=r"(a) : "l"(p));
    return a;
}
// 128B rows, 16B segs, XOR swizzle -> conflict-free stores + ldmatrix
__device__ __forceinline__ uint32_t swz(uint32_t base, int row, int seg) {
    return base + (uint32_t)row * 128u + (uint32_t)((seg ^ (row & 7)) << 4);
}
__device__ __forceinline__ void cpa16(uint32_t dst, const void* src) {
    asm volatile("cp.async.ca.shared.global [%0], [%1], 16;" :: "r"(dst), "l"(src) : "memory");
}
#define CP_COMMIT() asm volatile("cp.async.commit_group;" ::: "memory")
#define CP_WAIT(n)  asm volatile("cp.async.wait_group " #n ";" ::: "memory")
#define LDM_X4(r0, r1, r2, r3, a)                                                       \
    asm volatile("ldmatrix.sync.aligned.m8n8.x4.shared.b16 {%0,%1,%2,%3}, [%4];"        \
                 : "=r"(r0), "=r"(r1), "=r"(r2), "=r"(r3) : "r"(a))

__device__ __forceinline__ void mmabf(float* c, const uint32_t* a, const uint32_t* b) {
    asm volatile(
        "mma.sync.aligned.m16n8k16.row.col.f32.bf16.bf16.f32 "
        "{%0,%1,%2,%3}, {%4,%5,%6,%7}, {%8,%9}, {%0,%1,%2,%3};"
        : "+f"(c[0]), "+f"(c[1]), "+f"(c[2]), "+f"(c[3])
        : "r"(a[0]), "r"(a[1]), "r"(a[2]), "r"(a[3]), "r"(b[0]), "r"(b[1]));
}

// =================== prep kernels ===================
__global__ void zero_hc() {
    int i = blockIdx.x * blockDim.x + threadIdx.x;
    if (i < P_N * H_DIM) g_hb[0][i] = __float2bfloat16(0.0f);
    if (blockIdx.x == 0 && threadIdx.x < 128) g_flags[threadIdx.x] = 0u;
}

// permuted row r: q = (r>>3)&3, j = (r>>5)*8 + (r&7); orig row = q*H + j. bf16 convert.
__global__ void permute_weights(const float* __restrict__ Whh, const float* __restrict__ Wih,
                                const float* __restrict__ b_ih, const float* __restrict__ b_hh) {
    const int r = blockIdx.x;
    const int q = (r >> 3) & 3;
    const int j = (r >> 5) * 8 + (r & 7);
    const int orig = q * H_DIM + j;
    const float4* s1 = (const float4*)(Whh + (size_t)orig * H_DIM);
    __nv_bfloat162* d1 = (__nv_bfloat162*)(g_Whh_b + (size_t)r * H_DIM);
    for (int i = threadIdx.x; i < H_DIM / 4; i += blockDim.x) {
        const float4 v = s1[i];
        d1[i * 2 + 0] = __floats2bfloat162_rn(v.x, v.y);
        d1[i * 2 + 1] = __floats2bfloat162_rn(v.z, v.w);
    }
    const float4* s2 = (const float4*)(Wih + (size_t)orig * I_DIM);
    __nv_bfloat162* d2 = (__nv_bfloat162*)(g_Wih_b + (size_t)r * I_DIM);
    for (int i = threadIdx.x; i < I_DIM / 4; i += blockDim.x) {
        const float4 v = s2[i];
        d2[i * 2 + 0] = __floats2bfloat162_rn(v.x, v.y);
        d2[i * 2 + 1] = __floats2bfloat162_rn(v.z, v.w);
    }
    if (threadIdx.x == 0) g_bias_p[r] = b_ih[orig] + b_hh[orig];
}

// gather + convert: g_x[row] = bf16(emb[paths_flat[row]])
__global__ void gather_emb(const int* __restrict__ paths, const float* __restrict__ emb) {
    const int row = blockIdx.x * 2 + (threadIdx.x >> 7);
    const int k4 = (threadIdx.x & 127) * 4;
    const int tok = paths[row];
    const float4 v = *(const float4*)(emb + (size_t)tok * I_DIM + k4);
    __nv_bfloat162* d = (__nv_bfloat162*)(g_x + (size_t)row * I_DIM + k4);
    d[0] = __floats2bfloat162_rn(v.x, v.y);
    d[1] = __floats2bfloat162_rn(v.z, v.w);
}

// =================== embed GEMM (bf16): xWb = g_x @ Wih_b^T + bias ===================
// CTA 128x128, K=512 (8 chunks of 64). 8 warps 2m x 4n, warp 64x32. 3-stage, 2 CTA/SM.
#define E_STG 32768  // A 16KB + B 16KB

__global__ void __launch_bounds__(256, 2) gemm_embed_bf() {
    extern __shared__ char sm[];
    const uint32_t sb = smem_u32(sm);
    const int tid = threadIdx.x;
    const int lane = tid & 31, wid = tid >> 5;
    const int wm = wid >> 2, wn = wid & 3;
    const int gr = lane >> 2, tg = lane & 3;
    const int m0 = blockIdx.y * 128, n0 = blockIdx.x * 128;

    const int a_row_l = (lane & 7) + ((lane >> 3) & 1) * 8;
    const int a_seg_l = lane >> 4;
    const int b_row_l = wn * 32 + (lane & 7) + (lane >> 4) * 8;
    const int b_seg_l = (lane >> 3) & 1;

    float cfr[4][4][4];
    #pragma unroll
    for (int a = 0; a < 4; a++)
        #pragma unroll
        for (int b = 0; b < 4; b++)
            #pragma unroll
            for (int c = 0; c < 4; c++) cfr[a][b][c] = 0.0f;

    #define E_ISSUE(ch) do {                                                              \
        const uint32_t ab = sb + ((ch) % 3) * E_STG;                                      \
        const uint32_t bb = ab + 16384;                                                   \
        const int k0 = (ch) * 64;                                                         \
        _Pragma("unroll")                                                                 \
        for (int i = 0; i < 4; i++) {                                                     \
            const int idx = tid + i * 256;                                                \
            const int row = idx >> 3, seg = idx & 7;                                      \
            cpa16(swz(ab, row, seg), g_x + (size_t)(m0 + row) * I_DIM + k0 + seg * 8);    \
            cpa16(swz(bb, row, seg), g_Wih_b + (size_t)(n0 + row) * I_DIM + k0 + seg * 8);\
        }                                                                                 \
        CP_COMMIT();                                                                      \
    } while (0)

    E_ISSUE(0); E_ISSUE(1);

    for (int ch = 0; ch < 8; ch++) {
        if (ch < 7) CP_WAIT(1);
        else CP_WAIT(0);
        __syncthreads();
        if (ch + 2 < 8) E_ISSUE(ch + 2);

        const uint32_t ab = sb + (ch % 3) * E_STG;
        const uint32_t bb = ab + 16384;
        #pragma unroll
        for (int s = 0; s < 4; s++) {
            uint32_t af[4][4], bf[4][2];
            #pragma unroll
            for (int mf = 0; mf < 4; mf++)
                LDM_X4(af[mf][0], af[mf][1], af[mf][2], af[mf][3],
                       swz(ab, wm * 64 + mf * 16 + a_row_l, 2 * s + a_seg_l));
            #pragma unroll
            for (int h = 0; h < 2; h++)
                LDM_X4(bf[2 * h][0], bf[2 * h][1], bf[2 * h + 1][0], bf[2 * h + 1][1],
                       swz(bb, b_row_l + h * 16, 2 * s + b_seg_l));
            #pragma unroll
            for (int mf = 0; mf < 4; mf++)
                #pragma unroll
                for (int nf = 0; nf < 4; nf++)
                    mmabf(cfr[mf][nf], af[mf], bf[nf]);
        }
    }

    const int colw = n0 + wn * 32;
    #pragma unroll
    for (int mf = 0; mf < 4; mf++) {
        #pragma unroll
        for (int rr = 0; rr < 2; rr++) {
            const int row = m0 + wm * 64 + mf * 16 + gr + rr * 8;
            __nv_bfloat16* orow = g_xWb + (size_t)row * G4 + colw;
            #pragma unroll
            for (int q = 0; q < 4; q++) {
                const int cl = q * 8 + 2 * tg;
                const float2 bv = *(const float2*)&g_bias_p[colw + cl];
                *(__nv_bfloat162*)(orow + cl) = __floats2bfloat162_rn(
                    cfr[mf][q][rr * 2 + 0] + bv.x, cfr[mf][q][rr * 2 + 1] + bv.y);
            }
        }
    }
    #undef E_ISSUE
}

// =================== persistent LSTM: 64 steps, one launch ===================
// 128 CTAs (grid 32n x 4m), CTA tile 64p x 128g, K=1024 (16 chunks of 64), 4 stages.
// c lives in registers across all 64 steps; inter-step sync via flag-array barrier.
#define L_STG 24576  // A 8KB + B 16KB

__global__ void __launch_bounds__(256) lstm_persist(const int* __restrict__ lengths) {
    extern __shared__ char sm[];
    const uint32_t sb = smem_u32(sm);
    const int tid = threadIdx.x;
    const int lane = tid & 31, wid = tid >> 5;
    const int wm = wid >> 2, wn = wid & 3;
    const int gr = lane >> 2, tg = lane & 3;
    const int m0 = blockIdx.y * 64, n0 = blockIdx.x * 128;
    const int cta = blockIdx.y * 32 + blockIdx.x;

    const int a_row_l = (lane & 7) + ((lane >> 3) & 1) * 8;
    const int a_seg_l = lane >> 4;
    const int b_row_l = wn * 32 + (lane & 7) + (lane >> 4) * 8;
    const int b_seg_l = (lane >> 3) & 1;

    const int colw = n0 + wn * 32;
    const int jpair = (colw >> 5) * 8 + 2 * tg;

    int lenm1[2][2];
    #pragma unroll
    for (int mf = 0; mf < 2; mf++)
        #pragma unroll
        for (int rr = 0; rr < 2; rr++)
            lenm1[mf][rr] = lengths[m0 + wm * 32 + mf * 16 + gr + rr * 8] - 1;

    float creg[2][2][2] = {};   // cell state, register-resident for whole recurrence

    for (int step = 0; step < L_N; step++) {
        const __nv_bfloat16* __restrict__ A_g = g_hb[step & 1];
        __nv_bfloat16* __restrict__ h_next = g_hb[(step & 1) ^ 1];

        // B prologue (W_hh is step-invariant: overlap with barrier wait)
        #pragma unroll
        for (int pc = 0; pc < 3; pc++) {
            const uint32_t bb = sb + pc * L_STG + 8192;
            const int k0 = pc * 64;
            #pragma unroll
            for (int i = 0; i < 4; i++) {
                const int idx = tid + i * 256;
                const int row = idx >> 3, seg = idx & 7;
                cpa16(swz(bb, row, seg), g_Whh_b + (size_t)(n0 + row) * H_DIM + k0 + seg * 8);
            }
            CP_COMMIT();
        }
        // barrier: h(step) published by all CTAs
        if (step > 0 && tid < 128) {
            while (g_flags[tid] < (unsigned)step) { }
        }
        __syncthreads();
        __threadfence();
        // A prologue
        #pragma unroll
        for (int pc = 0; pc < 3; pc++) {
            const uint32_t ab = sb + pc * L_STG;
            const int k0 = pc * 64;
            #pragma unroll
            for (int i = 0; i < 2; i++) {
                const int idx = tid + i * 256;
                const int row = idx >> 3, seg = idx & 7;
                cpa16(swz(ab, row, seg), A_g + (size_t)(m0 + row) * H_DIM + k0 + seg * 8);
            }
            CP_COMMIT();
        }

        float cfr[2][4][4];
        #pragma unroll
        for (int a = 0; a < 2; a++)
            #pragma unroll
            for (int b = 0; b < 4; b++)
                #pragma unroll
                for (int c = 0; c < 4; c++) cfr[a][b][c] = 0.0f;

        // groups: B0,B1,B2,A0,A1,A2, C3..C15 — consume ch needs group ch+4 done
        for (int ch = 0; ch < 16; ch++) {
            if (ch < 14) CP_WAIT(2);
            else if (ch == 14) CP_WAIT(1);
            else CP_WAIT(0);
            __syncthreads();
            if (ch + 3 < 16) {
                const int cc = ch + 3;
                const uint32_t ab = sb + (cc & 3) * L_STG;
                const uint32_t bb = ab + 8192;
                const int k0 = cc * 64;
                #pragma unroll
                for (int i = 0; i < 2; i++) {
                    const int idx = tid + i * 256;
                    const int row = idx >> 3, seg = idx & 7;
                    cpa16(swz(ab, row, seg), A_g + (size_t)(m0 + row) * H_DIM + k0 + seg * 8);
                }
                #pragma unroll
                for (int i = 0; i < 4; i++) {
                    const int idx = tid + i * 256;
                    const int row = idx >> 3, seg = idx & 7;
                    cpa16(swz(bb, row, seg), g_Whh_b + (size_t)(n0 + row) * H_DIM + k0 + seg * 8);
                }
                CP_COMMIT();
            }

            const uint32_t ab = sb + (ch & 3) * L_STG;
            const uint32_t bb = ab + 8192;
            #pragma unroll
            for (int s = 0; s < 4; s++) {
                uint32_t af[2][4], bf[4][2];
                #pragma unroll
                for (int mf = 0; mf < 2; mf++)
                    LDM_X4(af[mf][0], af[mf][1], af[mf][2], af[mf][3],
                           swz(ab, wm * 32 + mf * 16 + a_row_l, 2 * s + a_seg_l));
                #pragma unroll
                for (int h = 0; h < 2; h++)
                    LDM_X4(bf[2 * h][0], bf[2 * h][1], bf[2 * h + 1][0], bf[2 * h + 1][1],
                           swz(bb, b_row_l + h * 16, 2 * s + b_seg_l));
                #pragma unroll
                for (int mf = 0; mf < 2; mf++)
                    #pragma unroll
                    for (int nf = 0; nf < 4; nf++)
                        mmabf(cfr[mf][nf], af[mf], bf[nf]);
            }
        }

        // epilogue: nfrag q = gate q; thread cols {2tg,2tg+1} = h-col pair
        #pragma unroll
        for (int mf = 0; mf < 2; mf++) {
            #pragma unroll
            for (int rr = 0; rr < 2; rr++) {
                const int p = m0 + wm * 32 + mf * 16 + gr + rr * 8;
                const size_t xb = (size_t)(p * L_N + step) * G4 + colw;
                float2 xw[4];
                #pragma unroll
                for (int q = 0; q < 4; q++)
                    xw[q] = __bfloat1622float2(
                        *(const __nv_bfloat162*)&g_xWb[xb + q * 8 + 2 * tg]);

                const float gi0 = cfr[mf][0][rr * 2 + 0] + xw[0].x;
                const float gf0 = cfr[mf][1][rr * 2 + 0] + xw[1].x;
                const float gg0 = cfr[mf][2][rr * 2 + 0] + xw[2].x;
                const float go0 = cfr[mf][3][rr * 2 + 0] + xw[3].x;
                const float gi1 = cfr[mf][0][rr * 2 + 1] + xw[0].y;
                const float gf1 = cfr[mf][1][rr * 2 + 1] + xw[1].y;
                const float gg1 = cfr[mf][2][rr * 2 + 1] + xw[2].y;
                const float go1 = cfr[mf][3][rr * 2 + 1] + xw[3].y;

                float c0 = sigm(gf0) * creg[mf][rr][0] + sigm(gi0) * tanhf(gg0);
                float c1 = sigm(gf1) * creg[mf][rr][1] + sigm(gi1) * tanhf(gg1);
                creg[mf][rr][0] = c0;
                creg[mf][rr][1] = c1;
                const float h0 = sigm(go0) * tanhf(c0);
                const float h1 = sigm(go1) * tanhf(c1);

                const int ci = p * H_DIM + jpair;
                *(__nv_bfloat162*)&h_next[ci] = __floats2bfloat162_rn(h0, h1);
                if (lenm1[mf][rr] == step) {
                    g_final[ci] = h0;
                    g_final[ci + 1] = h1;
                }
            }
        }
        __syncthreads();
        __threadfence();
        if (tid == 0) g_flags[cta] = (unsigned)(step + 1);
    }
}

// =================== tail (SIMT, small) ===================
__global__ void __launch_bounds__(256) gemm_proj(
    const float* __restrict__ W, const float* __restrict__ bias, const int sel)
{
    __shared__ __align__(16) float As[32 * 68];
    __shared__ __align__(16) float Bs[32 * 68];
    const float* __restrict__ A = (sel == 0) ? g_final : g_v;
    float* __restrict__ C = (sel == 0) ? g_v : g_attn;
    const int tid = threadIdx.x;
    const int m0 = blockIdx.y * 64, n0 = blockIdx.x * 64;
    const int ty = tid >> 4, tx = tid & 15;
    const int lr = tid >> 3, lc4 = (tid & 7) * 4;
    float acc[4][4] = {};
    for (int k0 = 0; k0 < H_DIM; k0 += 32) {
        #pragma unroll
        for (int h = 0; h < 2; h++) {
            const int r = lr + h * 32;
            const float4 a = *(const float4*)(A + (size_t)(m0 + r) * H_DIM + k0 + lc4);
            As[(lc4 + 0) * 68 + r] = a.x; As[(lc4 + 1) * 68 + r] = a.y;
            As[(lc4 + 2) * 68 + r] = a.z; As[(lc4 + 3) * 68 + r] = a.w;
            const float4 b = *(const float4*)(W + (size_t)(n0 + r) * H_DIM + k0 + lc4);
            Bs[(lc4 + 0) * 68 + r] = b.x; Bs[(lc4 + 1) * 68 + r] = b.y;
            Bs[(lc4 + 2) * 68 + r] = b.z; Bs[(lc4 + 3) * 68 + r] = b.w;
        }
        __syncthreads();
        #pragma unroll
        for (int k = 0; k < 32; k++) {
            const float4 a = *(const float4*)&As[k * 68 + ty * 4];
            const float4 b = *(const float4*)&Bs[k * 68 + tx * 4];
            const float av[4] = {a.x, a.y, a.z, a.w};
            const float bv[4] = {b.x, b.y, b.z, b.w};
            #pragma unroll
            for (int i = 0; i < 4; i++)
                #pragma unroll
                for (int j = 0; j < 4; j++)
                    acc[i][j] += av[i] * bv[j];
        }
        __syncthreads();
    }
    #pragma unroll
    for (int i = 0; i < 4; i++) {
        const int row = m0 + ty * 4 + i;
        #pragma unroll
        for (int j = 0; j < 4; j++)
            C[(size_t)row * H_DIM + n0 + tx * 4 + j] = acc[i][j] + bias[n0 + tx * 4 + j];
    }
}

__global__ void colmax() {
    const int j = blockIdx.x * 256 + threadIdx.x;
    float m = -INFINITY;
    for (int p = 0; p < P_N; p++) m = fmaxf(m, g_attn[(size_t)p * H_DIM + j]);
    g_pooled[j] = m;
}

__global__ void final_k(const float* __restrict__ W_lin,
                        const float* __restrict__ b_lin, float* __restrict__ out)
{
    __shared__ float r0[256], r1[256];
    const int tid = threadIdx.x;
    float a0 = 0.0f, a1 = 0.0f;
    for (int j = tid; j < H_DIM; j += 256) {
        const float pv = g_pooled[j];
        a0 += pv * W_lin[j];
        a1 += pv * W_lin[H_DIM + j];
    }
    r0[tid] = a0; r1[tid] = a1;
    __syncthreads();
    for (int s = 128; s > 0; s >>= 1) {
        if (tid < s) { r0[tid] += r0[tid + s]; r1[tid] += r1[tid + s]; }
        __syncthreads();
    }
    if (tid == 0) {
        out[0] = sigm(r0[0] + b_lin[0]);
        out[1] = sigm(r1[0] + b_lin[1]);
    }
}

extern "C" void kernel_launch(void* const* d_in, const int* in_sizes, int n_in,
                              void* d_out, int out_size) {
    const int*   paths   = (const int*)d_in[0];
    const int*   lengths = (const int*)d_in[1];
    const float* emb     = (const float*)d_in[2];
    const float* W_ih    = (const float*)d_in[3];
    const float* W_hh    = (const float*)d_in[4];
    const float* b_ih    = (const float*)d_in[5];
    const float* b_hh    = (const float*)d_in[6];
    const float* W_in    = (const float*)d_in[7];
    const float* b_in    = (const float*)d_in[8];
    const float* W_out   = (const float*)d_in[9];
    const float* b_out   = (const float*)d_in[10];
    const float* W_lin   = (const float*)d_in[11];
    const float* b_lin   = (const float*)d_in[12];
    float* out = (float*)d_out;

    static int attr_done = 0;
    if (!attr_done) {
        cudaFuncSetAttribute(gemm_embed_bf, cudaFuncAttributeMaxDynamicSharedMemorySize, 3 * E_STG);
        cudaFuncSetAttribute(lstm_persist,  cudaFuncAttributeMaxDynamicSharedMemorySize, 4 * L_STG);
        attr_done = 1;
    }

    permute_weights<<<G4, 128>>>(W_hh, W_ih, b_ih, b_hh);
    gather_emb<<<ROWS / 2, 256>>>(paths, emb);
    zero_hc<<<(P_N * H_DIM + 255) / 256, 256>>>();
    gemm_embed_bf<<<dim3(G4 / 128, ROWS / 128), 256, 3 * E_STG>>>();
    lstm_persist<<<dim3(G4 / 128, P_N / 64), 256, 4 * L_STG>>>(lengths);
    // seq_len==1 attention: softmax == 1, ctx == v; q/k projections are dead code
    gemm_proj<<<dim3(H_DIM / 64, P_N / 64), 256>>>(W_in + (size_t)2 * H_DIM * H_DIM,
                                                   b_in + 2 * H_DIM, 0);
    gemm_proj<<<dim3(H_DIM / 64, P_N / 64), 256>>>(W_out, b_out, 1);
    colmax<<<H_DIM / 256, 256>>>();
    final_k<<<1, 256>>>(W_lin, b_lin, out);
}